// round 13
// baseline (speedup 1.0000x reference)
#include <cuda_runtime.h>
#include <cuda_fp16.h>
#include <math.h>

#define N_NODES 100000
#define N_EDGES 1200000
#define COL_CAP (N_EDGES + 3 * N_NODES + 16)
#define HID 64
#define G_NUM 128
#define C_OUT 10
#define D_IN 3
#define EPS_BN 1e-5f

static __device__ __forceinline__ unsigned int h2_bits(__half2 h) {
    return *reinterpret_cast<unsigned int*>(&h);
}
static __device__ __forceinline__ __half2 bits_h2(unsigned int u) {
    return *reinterpret_cast<__half2*>(&u);
}

// -------- scratch (static device globals; no runtime allocation) --------
__device__ int   g_ecnt[N_NODES];
__device__ int   g_base[N_NODES];     // after k_base: aligned start; after fill: start+cnt
__device__ __align__(16) int g_col[COL_CAP];
__device__ int   g_tot;
__device__ __align__(16) __half g_xwh[N_NODES * HID];   // (h@W)*dinv, fp16
__device__ __align__(16) float  g_h  [N_NODES * HID];   // layer output, fp32

// -------- in-degree over real edges (4 edges/thread via int4) --------
__global__ void __launch_bounds__(256) k_deg(const int* __restrict__ ei) {
    int idx = blockIdx.x * blockDim.x + threadIdx.x;           // < E/4
    if (idx >= N_EDGES / 4) return;
    int4 d = ((const int4*)(ei + N_EDGES))[idx];
    atomicAdd(&g_ecnt[d.x], 1);
    atomicAdd(&g_ecnt[d.y], 1);
    atomicAdd(&g_ecnt[d.z], 1);
    atomicAdd(&g_ecnt[d.w], 1);
}

// -------- CSR bases, 4-aligned allocations (warp scan + atomic) --------
__global__ void k_base() {
    int i = blockIdx.x * blockDim.x + threadIdx.x;
    int lane = threadIdx.x & 31;
    int c = (i < N_NODES) ? g_ecnt[i] : 0;
    int alloc = (c + 3) & ~3;          // pad to multiple of 4 -> 16B-aligned segments
    int incl = alloc;
    #pragma unroll
    for (int off = 1; off < 32; off <<= 1) {
        int v = __shfl_up_sync(0xffffffffu, incl, off);
        if (lane >= off) incl += v;
    }
    int excl = incl - alloc;
    int wsum = __shfl_sync(0xffffffffu, incl, 31);
    int wbase = 0;
    if (lane == 31) wbase = atomicAdd(&g_tot, wsum);
    wbase = __shfl_sync(0xffffffffu, wbase, 31);
    if (i < N_NODES) g_base[i] = wbase + excl;
}

// -------- merged: CSR fill (blocks [0,NB_FILL)) + layer-0 linear (rest) -------
#define NB_FILL ((N_EDGES / 2 + 255) / 256)
#define NB_L0   ((N_NODES * 16 + 255) / 256)
__global__ void __launch_bounds__(256) k_fill_lin0(const int* __restrict__ ei,
                                                   const float* __restrict__ x,
                                                   const float* __restrict__ W0) {
    if (blockIdx.x < NB_FILL) {
        int idx = blockIdx.x * blockDim.x + threadIdx.x;       // < E/2
        if (idx >= N_EDGES / 2) return;
        int2 s = ((const int2*)ei)[idx];
        int2 d = ((const int2*)(ei + N_EDGES))[idx];
        int p0 = atomicAdd(&g_base[d.x], 1); g_col[p0] = s.x;
        int p1 = atomicAdd(&g_base[d.y], 1); g_col[p1] = s.y;
    } else {
        __shared__ float sW[D_IN * HID];
        int t = threadIdx.x;
        if (t < D_IN * HID) sW[t] = W0[t];
        __syncthreads();
        int idx = (blockIdx.x - NB_FILL) * blockDim.x + t;     // < N*16
        if (idx >= N_NODES * 16) return;
        int i = idx >> 4, j4 = idx & 15;
        float x0 = x[i * 3 + 0], x1 = x[i * 3 + 1], x2 = x[i * 3 + 2];
        float d = rsqrtf((float)(g_ecnt[i] + 1));
        float o[4];
        #pragma unroll
        for (int q = 0; q < 4; q++) {
            int j = 4 * j4 + q;
            o[q] = (x0 * sW[j] + x1 * sW[64 + j] + x2 * sW[128 + j]) * d;
        }
        uint2 pk;
        pk.x = h2_bits(__floats2half2_rn(o[0], o[1]));
        pk.y = h2_bits(__floats2half2_rn(o[2], o[3]));
        ((uint2*)g_xwh)[idx] = pk;
    }
}

// -------- hidden linear: register-tiled GEMM, 64x64/block, fp16 output -------
__global__ void __launch_bounds__(256) k_linh(const float* __restrict__ W) {
    __shared__ float sW [HID * HID];   // k-major: sW[k*64 + j]
    __shared__ float shT[HID * HID];   // transposed: shT[k*64 + node]
    int t = threadIdx.x;
    int node0 = blockIdx.x * 64;

    for (int q = t; q < 1024; q += 256)
        ((float4*)sW)[q] = ((const float4*)W)[q];

    int ln = t & 63;
    int c0 = t >> 6;
    #pragma unroll
    for (int cc = c0; cc < 16; cc += 4) {
        int gi = node0 + ln;
        float4 v = make_float4(0.f, 0.f, 0.f, 0.f);
        if (gi < N_NODES) v = ((const float4*)g_h)[gi * 16 + cc];
        shT[(4 * cc + 0) * 64 + ln] = v.x;
        shT[(4 * cc + 1) * 64 + ln] = v.y;
        shT[(4 * cc + 2) * 64 + ln] = v.z;
        shT[(4 * cc + 3) * 64 + ln] = v.w;
    }
    __syncthreads();

    int a = t >> 4;
    int b = t & 15;
    float4 acc0 = make_float4(0.f, 0.f, 0.f, 0.f);
    float4 acc1 = acc0, acc2 = acc0, acc3 = acc0;

    #pragma unroll 8
    for (int k = 0; k < 64; k++) {
        float4 vN = *(const float4*)&shT[k * 64 + 4 * a];
        float4 vW = *(const float4*)&sW [k * 64 + 4 * b];
        acc0.x += vN.x * vW.x; acc0.y += vN.x * vW.y; acc0.z += vN.x * vW.z; acc0.w += vN.x * vW.w;
        acc1.x += vN.y * vW.x; acc1.y += vN.y * vW.y; acc1.z += vN.y * vW.z; acc1.w += vN.y * vW.w;
        acc2.x += vN.z * vW.x; acc2.y += vN.z * vW.y; acc2.z += vN.z * vW.z; acc2.w += vN.z * vW.w;
        acc3.x += vN.w * vW.x; acc3.y += vN.w * vW.y; acc3.z += vN.w * vW.z; acc3.w += vN.w * vW.w;
    }

    float4 accs[4] = {acc0, acc1, acc2, acc3};
    #pragma unroll
    for (int r = 0; r < 4; r++) {
        int i = node0 + 4 * a + r;
        if (i < N_NODES) {
            float d = rsqrtf((float)(g_ecnt[i] + 1));
            float4 o = accs[r];
            uint2 pk;
            pk.x = h2_bits(__floats2half2_rn(o.x * d, o.y * d));
            pk.y = h2_bits(__floats2half2_rn(o.z * d, o.w * d));
            ((uint2*)g_xwh)[i * 16 + b] = pk;
        }
    }
}

// -------- CSR gather: 8 threads/node, uint4 (16B) rows, fused BN --------------
__global__ void __launch_bounds__(128) k_gather(const float* __restrict__ bb,
                                                const float* __restrict__ gamma,
                                                const float* __restrict__ beta,
                                                const float* __restrict__ mean,
                                                const float* __restrict__ var, int relu) {
    int t = threadIdx.x;
    int node = blockIdx.x * 16 + (t >> 3);   // 16 nodes / 128-thread block
    int j8 = t & 7;                          // which 16B chunk of the 128B row
    const uint4* xw4 = (const uint4*)g_xwh;  // row = 8 uint4

    int cnt  = g_ecnt[node];
    int base = g_base[node] - cnt;           // start (4-aligned)

    uint4 self = xw4[node * 8 + j8];
    float2 f0 = __half22float2(bits_h2(self.x));
    float2 f1 = __half22float2(bits_h2(self.y));
    float2 f2 = __half22float2(bits_h2(self.z));
    float2 f3 = __half22float2(bits_h2(self.w));
    float4 accA = make_float4(f0.x, f0.y, f1.x, f1.y);
    float4 accB = make_float4(f2.x, f2.y, f3.x, f3.y);

    const int4* c4p = (const int4*)(g_col + base);   // 16B-aligned
    int k = 0;
    for (; k + 4 <= cnt; k += 4) {
        int4 c4 = __ldg(&c4p[k >> 2]);
        uint4 r0 = __ldg(&xw4[c4.x * 8 + j8]);
        uint4 r1 = __ldg(&xw4[c4.y * 8 + j8]);
        uint4 r2 = __ldg(&xw4[c4.z * 8 + j8]);
        uint4 r3 = __ldg(&xw4[c4.w * 8 + j8]);
        __half2 sx = __hadd2(__hadd2(bits_h2(r0.x), bits_h2(r1.x)),
                             __hadd2(bits_h2(r2.x), bits_h2(r3.x)));
        __half2 sy = __hadd2(__hadd2(bits_h2(r0.y), bits_h2(r1.y)),
                             __hadd2(bits_h2(r2.y), bits_h2(r3.y)));
        __half2 sz = __hadd2(__hadd2(bits_h2(r0.z), bits_h2(r1.z)),
                             __hadd2(bits_h2(r2.z), bits_h2(r3.z)));
        __half2 sw = __hadd2(__hadd2(bits_h2(r0.w), bits_h2(r1.w)),
                             __hadd2(bits_h2(r2.w), bits_h2(r3.w)));
        float2 gx = __half22float2(sx);
        float2 gy = __half22float2(sy);
        float2 gz = __half22float2(sz);
        float2 gw = __half22float2(sw);
        accA.x += gx.x; accA.y += gx.y; accA.z += gy.x; accA.w += gy.y;
        accB.x += gz.x; accB.y += gz.y; accB.z += gw.x; accB.w += gw.y;
    }
    for (; k < cnt; k++) {
        int s = __ldg(&g_col[base + k]);
        uint4 r = __ldg(&xw4[s * 8 + j8]);
        float2 a0 = __half22float2(bits_h2(r.x));
        float2 a1 = __half22float2(bits_h2(r.y));
        float2 a2 = __half22float2(bits_h2(r.z));
        float2 a3 = __half22float2(bits_h2(r.w));
        accA.x += a0.x; accA.y += a0.y; accA.z += a1.x; accA.w += a1.y;
        accB.x += a2.x; accB.y += a2.y; accB.z += a3.x; accB.w += a3.y;
    }

    float d = rsqrtf((float)(cnt + 1));
    int c8 = 2 * j8;                         // float4 index for first 4 cols
    float4 vbA  = ((const float4*)bb)[c8],     vbB  = ((const float4*)bb)[c8 + 1];
    float4 vgA  = ((const float4*)gamma)[c8],  vgB  = ((const float4*)gamma)[c8 + 1];
    float4 vtA  = ((const float4*)beta)[c8],   vtB  = ((const float4*)beta)[c8 + 1];
    float4 vmA  = ((const float4*)mean)[c8],   vmB  = ((const float4*)mean)[c8 + 1];
    float4 vvA  = ((const float4*)var)[c8],    vvB  = ((const float4*)var)[c8 + 1];
    float4 oA, oB;
    oA.x = (accA.x * d + vbA.x - vmA.x) * (vgA.x * rsqrtf(vvA.x + EPS_BN)) + vtA.x;
    oA.y = (accA.y * d + vbA.y - vmA.y) * (vgA.y * rsqrtf(vvA.y + EPS_BN)) + vtA.y;
    oA.z = (accA.z * d + vbA.z - vmA.z) * (vgA.z * rsqrtf(vvA.z + EPS_BN)) + vtA.z;
    oA.w = (accA.w * d + vbA.w - vmA.w) * (vgA.w * rsqrtf(vvA.w + EPS_BN)) + vtA.w;
    oB.x = (accB.x * d + vbB.x - vmB.x) * (vgB.x * rsqrtf(vvB.x + EPS_BN)) + vtB.x;
    oB.y = (accB.y * d + vbB.y - vmB.y) * (vgB.y * rsqrtf(vvB.y + EPS_BN)) + vtB.y;
    oB.z = (accB.z * d + vbB.z - vmB.z) * (vgB.z * rsqrtf(vvB.z + EPS_BN)) + vtB.z;
    oB.w = (accB.w * d + vbB.w - vmB.w) * (vgB.w * rsqrtf(vvB.w + EPS_BN)) + vtB.w;
    if (relu) {
        oA.x = fmaxf(oA.x, 0.f); oA.y = fmaxf(oA.y, 0.f);
        oA.z = fmaxf(oA.z, 0.f); oA.w = fmaxf(oA.w, 0.f);
        oB.x = fmaxf(oB.x, 0.f); oB.y = fmaxf(oB.y, 0.f);
        oB.z = fmaxf(oB.z, 0.f); oB.w = fmaxf(oB.w, 0.f);
    }
    ((float4*)g_h)[node * 16 + c8]     = oA;
    ((float4*)g_h)[node * 16 + c8 + 1] = oB;
}

// -------- fused pooling + classifier + log_softmax: 1 block / graph -----------
__global__ void __launch_bounds__(256) k_poolcls(const int* __restrict__ batch,
                                                 const float* __restrict__ Wc1,
                                                 const float* __restrict__ bc1,
                                                 const float* __restrict__ Wc2,
                                                 const float* __restrict__ bc2,
                                                 float* __restrict__ out) {
    __shared__ int s_se[2];
    __shared__ float ssum[16 * 65];
    __shared__ float smax[16 * 65];
    __shared__ float gv[2 * HID];
    __shared__ float hc[HID];
    __shared__ float lg[C_OUT];
    __shared__ float s_lse;

    int g = blockIdx.x;
    int t = threadIdx.x;

    if (t == 0) {
        int lo = 0, hi = N_NODES;
        while (lo < hi) { int m = (lo + hi) >> 1; if (batch[m] < g) lo = m + 1; else hi = m; }
        s_se[0] = lo;
        lo = 0; hi = N_NODES;
        while (lo < hi) { int m = (lo + hi) >> 1; if (batch[m] < g + 1) lo = m + 1; else hi = m; }
        s_se[1] = lo;
    }
    __syncthreads();
    int start = s_se[0], end = s_se[1];

    int r  = t >> 4;
    int j4 = t & 15;
    const float4* h4 = (const float4*)g_h;
    float4 sum = make_float4(0.f, 0.f, 0.f, 0.f);
    float4 mx  = make_float4(-INFINITY, -INFINITY, -INFINITY, -INFINITY);
    for (int i = start + r; i < end; i += 16) {
        float4 v = h4[i * 16 + j4];
        sum.x += v.x; sum.y += v.y; sum.z += v.z; sum.w += v.w;
        mx.x = fmaxf(mx.x, v.x); mx.y = fmaxf(mx.y, v.y);
        mx.z = fmaxf(mx.z, v.z); mx.w = fmaxf(mx.w, v.w);
    }
    ssum[r * 65 + 4 * j4 + 0] = sum.x; ssum[r * 65 + 4 * j4 + 1] = sum.y;
    ssum[r * 65 + 4 * j4 + 2] = sum.z; ssum[r * 65 + 4 * j4 + 3] = sum.w;
    smax[r * 65 + 4 * j4 + 0] = mx.x;  smax[r * 65 + 4 * j4 + 1] = mx.y;
    smax[r * 65 + 4 * j4 + 2] = mx.z;  smax[r * 65 + 4 * j4 + 3] = mx.w;
    __syncthreads();

    if (t < HID) {
        float s = 0.f, m = -INFINITY;
        #pragma unroll
        for (int q = 0; q < 16; q++) {
            s += ssum[q * 65 + t];
            m = fmaxf(m, smax[q * 65 + t]);
        }
        gv[t]       = s / (float)(end - start);
        gv[HID + t] = m;
    }
    __syncthreads();

    if (t < HID) {
        float s = bc1[t];
        #pragma unroll 16
        for (int k = 0; k < 2 * HID; k++) s += gv[k] * Wc1[k * HID + t];
        hc[t] = fmaxf(s, 0.f);
    }
    __syncthreads();

    if (t < C_OUT) {
        float l = bc2[t];
        #pragma unroll 16
        for (int j = 0; j < HID; j++) l += hc[j] * Wc2[j * C_OUT + t];
        lg[t] = l;
    }
    __syncthreads();

    if (t == 0) {
        float m = -INFINITY;
        #pragma unroll
        for (int c = 0; c < C_OUT; c++) m = fmaxf(m, lg[c]);
        float se = 0.f;
        #pragma unroll
        for (int c = 0; c < C_OUT; c++) se += expf(lg[c] - m);
        s_lse = m + logf(se);
    }
    __syncthreads();
    if (t < C_OUT) out[g * C_OUT + t] = lg[t] - s_lse;
}

extern "C" void kernel_launch(void* const* d_in, const int* in_sizes, int n_in,
                              void* d_out, int out_size) {
    const float* x     = (const float*)d_in[0];
    const int*   ei    = (const int*)  d_in[1];
    const int*   batch = (const int*)  d_in[2];
    // d_in[3] = num_graphs (constant 128, unused)
    const float* W0    = (const float*)d_in[4];
    const float* Ws    = (const float*)d_in[5];
    const float* bs    = (const float*)d_in[6];
    const float* gamma = (const float*)d_in[7];
    const float* beta  = (const float*)d_in[8];
    const float* rmean = (const float*)d_in[9];
    const float* rvar  = (const float*)d_in[10];
    const float* Wc1   = (const float*)d_in[11];
    const float* bc1   = (const float*)d_in[12];
    const float* Wc2   = (const float*)d_in[13];
    const float* bc2   = (const float*)d_in[14];
    float* out = (float*)d_out;

    const int NB_N    = (N_NODES + 255) / 256;
    const int NB_E4   = (N_EDGES / 4 + 255) / 256;
    const int NB_GAT  = N_NODES / 16;          // 6250, 128-thread blocks, 8 thr/node
    const int NB_GEMM = (N_NODES + 63) / 64;

    // zero-init counters via graph memset nodes
    void* p_ecnt = 0; void* p_tot = 0;
    cudaGetSymbolAddress(&p_ecnt, g_ecnt);
    cudaGetSymbolAddress(&p_tot,  g_tot);
    cudaMemsetAsync(p_ecnt, 0, N_NODES * sizeof(int));
    cudaMemsetAsync(p_tot,  0, sizeof(int));

    // CSR build (fill overlapped with layer-0 linear in one launch)
    k_deg      <<<NB_E4, 256>>>(ei);
    k_base     <<<NB_N, 256>>>();
    k_fill_lin0<<<NB_FILL + NB_L0, 256>>>(ei, x, W0);

    // layer 0 aggregate
    k_gather<<<NB_GAT, 128>>>(bs + 0 * HID, gamma + 0 * HID, beta + 0 * HID,
                              rmean + 0 * HID, rvar + 0 * HID, 1);
    // layer 1
    k_linh  <<<NB_GEMM, 256>>>(Ws + 0 * HID * HID);
    k_gather<<<NB_GAT, 128>>>(bs + 1 * HID, gamma + 1 * HID, beta + 1 * HID,
                              rmean + 1 * HID, rvar + 1 * HID, 1);
    // layer 2 (no relu)
    k_linh  <<<NB_GEMM, 256>>>(Ws + 1 * HID * HID);
    k_gather<<<NB_GAT, 128>>>(bs + 2 * HID, gamma + 2 * HID, beta + 2 * HID,
                              rmean + 2 * HID, rvar + 2 * HID, 0);

    // fused pooling + classifier
    k_poolcls<<<G_NUM, 256>>>(batch, Wc1, bc1, Wc2, bc2, out);
}